// round 15
// baseline (speedup 1.0000x reference)
#include <cuda_runtime.h>
#include <cuda_bf16.h>
#include <cuda_fp16.h>
#include <cstdint>
#include <cstddef>

#define NN 100000
#define NE 1600000
#define IN_DIM 128
#define HID_DIM 128
#define LAT_DIM 64
#define NB 391  // (NN + 255) / 256, scan blocks

// ---------------------------------------------------------------------------
// Scratch (no cudaMalloc allowed)
// ---------------------------------------------------------------------------
__device__ __half g_t1[(size_t)NN * HID_DIM];   // x @ W1           (fp16)
__device__ float  g_agg1[(size_t)NN * HID_DIM]; // A @ t1           (fp32)
__device__ __half g_t2[(size_t)NN * LAT_DIM];   // relu(agg1+b1)@W2 (fp16)
__device__ int    g_deg[NN];
__device__ int    g_off[NN + 1];
__device__ int    g_cur[NN];
__device__ int    g_bsum[512];
__device__ int    g_boff[512];
__device__ int2   g_edge[NE];                   // dst-sorted (src, val_bits)
// W transposed to [N][K=128], bf16 hi/lo split
__device__ __nv_bfloat16 g_w1hi[128 * 128];
__device__ __nv_bfloat16 g_w1lo[128 * 128];
__device__ __nv_bfloat16 g_w2hi[64 * 128];
__device__ __nv_bfloat16 g_w2lo[64 * 128];

// ---------------------------------------------------------------------------
// warp-MMA helpers (baseline PTX, works on plain compute_103 target)
// ---------------------------------------------------------------------------
__device__ __forceinline__ uint32_t smem_u32(const void* p) {
    uint32_t a;
    asm("{ .reg .u64 t; cvta.to.shared.u64 t, %1; cvt.u32.u64 %0, t; }" : "=r"(a) : "l"(p));
    return a;
}
__device__ __forceinline__ void ldsm4(uint32_t addr, uint32_t& r0, uint32_t& r1,
                                      uint32_t& r2, uint32_t& r3) {
    asm volatile("ldmatrix.sync.aligned.m8n8.x4.shared.b16 {%0,%1,%2,%3}, [%4];"
                 : "=r"(r0), "=r"(r1), "=r"(r2), "=r"(r3) : "r"(addr));
}
__device__ __forceinline__ void mma16816(float* d, const uint32_t* a, const uint32_t* b) {
    asm volatile("mma.sync.aligned.m16n8k16.row.col.f32.bf16.bf16.f32 "
                 "{%0,%1,%2,%3}, {%4,%5,%6,%7}, {%8,%9}, {%0,%1,%2,%3};"
                 : "+f"(d[0]), "+f"(d[1]), "+f"(d[2]), "+f"(d[3])
                 : "r"(a[0]), "r"(a[1]), "r"(a[2]), "r"(a[3]), "r"(b[0]), "r"(b[1]));
}
__device__ __forceinline__ uint32_t pack_bf16x2(__nv_bfloat16 a, __nv_bfloat16 b) {
    return (uint32_t)__bfloat16_as_ushort(a) | ((uint32_t)__bfloat16_as_ushort(b) << 16);
}

// ---------------------------------------------------------------------------
// prep_w: W[k][n] row-major -> Wt[n][k] bf16 hi/lo
// ---------------------------------------------------------------------------
__global__ void __launch_bounds__(256) prep_w(const float* __restrict__ W, int N,
                                              __nv_bfloat16* __restrict__ hi,
                                              __nv_bfloat16* __restrict__ lo) {
    const int total = 128 * N;
    for (int idx = blockIdx.x * blockDim.x + threadIdx.x; idx < total;
         idx += gridDim.x * blockDim.x) {
        const int k = idx / N, n = idx % N;
        const float v = W[idx];
        const __nv_bfloat16 h = __float2bfloat16(v);
        const __nv_bfloat16 l = __float2bfloat16(v - __bfloat162float(h));
        hi[n * 128 + k] = h;
        lo[n * 128 + k] = l;
    }
}

// ---------------------------------------------------------------------------
// HMMA GEMM: out16[128 rows, N] = X[rows,128] @ Wt  (bf16-split, 3 passes)
// ---------------------------------------------------------------------------
template <int N_DIM, bool RELU_BIAS>
__global__ void __launch_bounds__(256) gemm_mma(const float* __restrict__ X,
                                                const float* __restrict__ BIAS,
                                                const __nv_bfloat16* __restrict__ WHI,
                                                const __nv_bfloat16* __restrict__ WLO,
                                                __half* __restrict__ out) {
    extern __shared__ __nv_bfloat16 sm[];
    constexpr int LDS = 136;                 // padded row stride (elements)
    constexpr int AHI = 0;
    constexpr int ALO = 128 * LDS;
    constexpr int BHI = 2 * 128 * LDS;
    constexpr int BLO = BHI + N_DIM * LDS;
    constexpr int WN = N_DIM / 2;            // warp n-extent
    constexpr int NT = WN / 8;               // n-tiles per warp

    const int tid = threadIdx.x;
    const int wid = tid >> 5, lane = tid & 31;
    const int row0 = blockIdx.x * 128;
    const uint32_t smb = smem_u32(sm);

    // copy Wt hi/lo into padded smem rows (16B chunks)
    {
        const uint4* sh = (const uint4*)WHI;
        const uint4* sl = (const uint4*)WLO;
        for (int i = tid; i < N_DIM * 16; i += 256) {
            const int r = i >> 4, c = i & 15;
            *(uint4*)(sm + BHI + r * LDS + c * 8) = sh[i];
            *(uint4*)(sm + BLO + r * LDS + c * 8) = sl[i];
        }
    }

    // load + (optional bias/relu) + hi/lo split-convert the A tile
    {
        const int r = tid >> 1;
        const int kh = (tid & 1) * 64;
        const bool ok = (row0 + r) < NN;
        uint32_t* ahi = (uint32_t*)(sm + AHI + r * LDS + kh);
        uint32_t* alo = (uint32_t*)(sm + ALO + r * LDS + kh);
#pragma unroll
        for (int i = 0; i < 16; i++) {
            float4 v = make_float4(0.f, 0.f, 0.f, 0.f);
            if (ok) {
                v = *(const float4*)(X + (size_t)(row0 + r) * 128 + kh + i * 4);
                if (RELU_BIAS) {
                    const float4 bv = *(const float4*)(BIAS + kh + i * 4);
                    v.x = fmaxf(v.x + bv.x, 0.f);
                    v.y = fmaxf(v.y + bv.y, 0.f);
                    v.z = fmaxf(v.z + bv.z, 0.f);
                    v.w = fmaxf(v.w + bv.w, 0.f);
                }
            }
            const __nv_bfloat16 h0 = __float2bfloat16(v.x), h1 = __float2bfloat16(v.y);
            const __nv_bfloat16 h2 = __float2bfloat16(v.z), h3 = __float2bfloat16(v.w);
            const __nv_bfloat16 l0 = __float2bfloat16(v.x - __bfloat162float(h0));
            const __nv_bfloat16 l1 = __float2bfloat16(v.y - __bfloat162float(h1));
            const __nv_bfloat16 l2 = __float2bfloat16(v.z - __bfloat162float(h2));
            const __nv_bfloat16 l3 = __float2bfloat16(v.w - __bfloat162float(h3));
            ahi[i * 2] = pack_bf16x2(h0, h1);
            ahi[i * 2 + 1] = pack_bf16x2(h2, h3);
            alo[i * 2] = pack_bf16x2(l0, l1);
            alo[i * 2 + 1] = pack_bf16x2(l2, l3);
        }
    }
    __syncthreads();

    const int m0 = (wid & 3) * 32;
    const int n0 = (wid >> 2) * WN;

    float acc[2][NT][4];
#pragma unroll
    for (int mt = 0; mt < 2; mt++)
#pragma unroll
        for (int nt = 0; nt < NT; nt++)
#pragma unroll
            for (int j = 0; j < 4; j++) acc[mt][nt][j] = 0.f;

#pragma unroll
    for (int p = 0; p < 3; p++) {
        const int aoff = (p == 2) ? ALO : AHI;
        const int boff = (p == 1) ? BLO : BHI;
        const uint32_t abase = smb + 2 * aoff;
        const uint32_t bbase = smb + 2 * boff;
#pragma unroll
        for (int ks = 0; ks < 8; ks++) {
            uint32_t af[2][4];
#pragma unroll
            for (int mt = 0; mt < 2; mt++) {
                const int r = m0 + mt * 16 + (lane & 7) + ((lane >> 3) & 1) * 8;
                const int kk = ks * 16 + (lane >> 4) * 8;
                ldsm4(abase + (uint32_t)(r * LDS + kk) * 2,
                      af[mt][0], af[mt][1], af[mt][2], af[mt][3]);
            }
            uint32_t bf[NT][2];
#pragma unroll
            for (int np = 0; np < NT / 2; np++) {
                const int r = n0 + np * 16 + (lane >> 4) * 8 + (lane & 7);
                const int kk = ks * 16 + ((lane >> 3) & 1) * 8;
                uint32_t t0, t1, t2, t3;
                ldsm4(bbase + (uint32_t)(r * LDS + kk) * 2, t0, t1, t2, t3);
                bf[2 * np][0] = t0; bf[2 * np][1] = t1;
                bf[2 * np + 1][0] = t2; bf[2 * np + 1][1] = t3;
            }
#pragma unroll
            for (int mt = 0; mt < 2; mt++)
#pragma unroll
                for (int nt = 0; nt < NT; nt++) mma16816(acc[mt][nt], af[mt], bf[nt]);
        }
    }

    // epilogue: D frag -> global fp16
#pragma unroll
    for (int mt = 0; mt < 2; mt++) {
        const int r = row0 + m0 + mt * 16 + (lane >> 2);
#pragma unroll
        for (int nt = 0; nt < NT; nt++) {
            const int c = n0 + nt * 8 + (lane & 3) * 2;
            if (r < NN)
                *(__half2*)(out + (size_t)r * N_DIM + c) =
                    __floats2half2_rn(acc[mt][nt][0], acc[mt][nt][1]);
            if (r + 8 < NN)
                *(__half2*)(out + (size_t)(r + 8) * N_DIM + c) =
                    __floats2half2_rn(acc[mt][nt][2], acc[mt][nt][3]);
        }
    }
}

// ---------------------------------------------------------------------------
// CSR build: histogram -> 3-kernel scan -> scatter (deg zeroed via memset)
// ---------------------------------------------------------------------------
__global__ void __launch_bounds__(256) hist_kernel(const int* __restrict__ dst, int E) {
    const int i = blockIdx.x * blockDim.x + threadIdx.x;
    if (i < E) atomicAdd(&g_deg[dst[i]], 1);
}

__global__ void __launch_bounds__(256) scan_a() {
    __shared__ int s[256];
    const int t = threadIdx.x;
    const int i = blockIdx.x * 256 + t;
    s[t] = (i < NN) ? g_deg[i] : 0;
    __syncthreads();
#pragma unroll
    for (int d = 128; d > 0; d >>= 1) {
        if (t < d) s[t] += s[t + d];
        __syncthreads();
    }
    if (t == 0) g_bsum[blockIdx.x] = s[0];
}

__global__ void __launch_bounds__(512) scan_b(int E) {
    __shared__ int s[512];
    const int t = threadIdx.x;
    const int v = (t < NB) ? g_bsum[t] : 0;
    s[t] = v;
    __syncthreads();
    for (int d = 1; d < 512; d <<= 1) {
        const int a = (t >= d) ? s[t - d] : 0;
        __syncthreads();
        s[t] += a;
        __syncthreads();
    }
    if (t < NB) g_boff[t] = s[t] - v;
    if (t == 0) g_off[NN] = E;
}

__global__ void __launch_bounds__(256) scan_c() {
    __shared__ int s[256];
    const int t = threadIdx.x;
    const int i = blockIdx.x * 256 + t;
    const int v = (i < NN) ? g_deg[i] : 0;
    s[t] = v;
    __syncthreads();
    for (int d = 1; d < 256; d <<= 1) {
        const int a = (t >= d) ? s[t - d] : 0;
        __syncthreads();
        s[t] += a;
        __syncthreads();
    }
    if (i < NN) {
        const int excl = s[t] - v + g_boff[blockIdx.x];
        g_off[i] = excl;
        g_cur[i] = excl;
    }
}

__global__ void __launch_bounds__(256) scatter_kernel(const int* __restrict__ src,
                                                      const int* __restrict__ dst,
                                                      const float* __restrict__ vals, int E) {
    const int i = blockIdx.x * blockDim.x + threadIdx.x;
    if (i < E) {
        const int d = dst[i];
        const int p = atomicAdd(&g_cur[d], 1);
        g_edge[p] = make_int2(src[i], __float_as_int(vals[i]));
    }
}

// ---------------------------------------------------------------------------
// gather SpMM, wide lanes: spmm128 -> 8 lanes/row (32B/lane), spmm64 ->
// 4 lanes/row. Same 4-edge batch structure; 8 independent gathers in flight
// per lane per batch (2x champion MLP); direct g_edge record reads.
// ---------------------------------------------------------------------------
__global__ void __launch_bounds__(256) spmm_gather128(const __half* __restrict__ X,
                                                      float* __restrict__ Y) {
    const int row = (blockIdx.x * blockDim.x + threadIdx.x) >> 3;  // 8 lanes/row
    if (row >= NN) return;
    const int c2 = (threadIdx.x & 7) * 2;  // first of 2 uint4 indices (32B)
    const int beg = g_off[row], end = g_off[row + 1];
    const uint4* Xv = (const uint4*)X;

    float acc[16];
#pragma unroll
    for (int i = 0; i < 16; i++) acc[i] = 0.f;

    int e = beg;
    for (; e + 4 <= end; e += 4) {
        const int2 r0 = g_edge[e], r1 = g_edge[e + 1];
        const int2 r2 = g_edge[e + 2], r3 = g_edge[e + 3];
        uint4 xa[4], xb[4];
        xa[0] = Xv[(size_t)r0.x * 16 + c2];     xb[0] = Xv[(size_t)r0.x * 16 + c2 + 1];
        xa[1] = Xv[(size_t)r1.x * 16 + c2];     xb[1] = Xv[(size_t)r1.x * 16 + c2 + 1];
        xa[2] = Xv[(size_t)r2.x * 16 + c2];     xb[2] = Xv[(size_t)r2.x * 16 + c2 + 1];
        xa[3] = Xv[(size_t)r3.x * 16 + c2];     xb[3] = Xv[(size_t)r3.x * 16 + c2 + 1];
        const float v[4] = {__int_as_float(r0.y), __int_as_float(r1.y),
                            __int_as_float(r2.y), __int_as_float(r3.y)};
#pragma unroll
        for (int j = 0; j < 4; j++) {
            const __half2* ha = (const __half2*)&xa[j];
            const __half2* hb = (const __half2*)&xb[j];
#pragma unroll
            for (int i = 0; i < 4; i++) {
                const float2 fa = __half22float2(ha[i]);
                const float2 fb = __half22float2(hb[i]);
                acc[2 * i]     += v[j] * fa.x;
                acc[2 * i + 1] += v[j] * fa.y;
                acc[8 + 2 * i]     += v[j] * fb.x;
                acc[8 + 2 * i + 1] += v[j] * fb.y;
            }
        }
    }
    for (; e < end; e++) {
        const int2 ee = g_edge[e];
        const float v = __int_as_float(ee.y);
        const uint4 xa = Xv[(size_t)ee.x * 16 + c2];
        const uint4 xb = Xv[(size_t)ee.x * 16 + c2 + 1];
        const __half2* ha = (const __half2*)&xa;
        const __half2* hb = (const __half2*)&xb;
#pragma unroll
        for (int i = 0; i < 4; i++) {
            const float2 fa = __half22float2(ha[i]);
            const float2 fb = __half22float2(hb[i]);
            acc[2 * i] += v * fa.x;
            acc[2 * i + 1] += v * fa.y;
            acc[8 + 2 * i] += v * fb.x;
            acc[8 + 2 * i + 1] += v * fb.y;
        }
    }
    float* yp = Y + (size_t)row * 128 + c2 * 8;
    *(float4*)(yp)      = make_float4(acc[0], acc[1], acc[2], acc[3]);
    *(float4*)(yp + 4)  = make_float4(acc[4], acc[5], acc[6], acc[7]);
    *(float4*)(yp + 8)  = make_float4(acc[8], acc[9], acc[10], acc[11]);
    *(float4*)(yp + 12) = make_float4(acc[12], acc[13], acc[14], acc[15]);
}

__global__ void __launch_bounds__(256) spmm_gather64(const __half* __restrict__ X,
                                                     const float* __restrict__ B2,
                                                     float* __restrict__ Y) {
    const int row = (blockIdx.x * blockDim.x + threadIdx.x) >> 2;  // 4 lanes/row
    if (row >= NN) return;
    const int c2 = (threadIdx.x & 3) * 2;  // first of 2 uint4 indices (32B)
    const int beg = g_off[row], end = g_off[row + 1];
    const uint4* Xv = (const uint4*)X;

    float acc[16];
#pragma unroll
    for (int i = 0; i < 16; i++) acc[i] = 0.f;

    int e = beg;
    for (; e + 4 <= end; e += 4) {
        const int2 r0 = g_edge[e], r1 = g_edge[e + 1];
        const int2 r2 = g_edge[e + 2], r3 = g_edge[e + 3];
        uint4 xa[4], xb[4];
        xa[0] = Xv[(size_t)r0.x * 8 + c2];     xb[0] = Xv[(size_t)r0.x * 8 + c2 + 1];
        xa[1] = Xv[(size_t)r1.x * 8 + c2];     xb[1] = Xv[(size_t)r1.x * 8 + c2 + 1];
        xa[2] = Xv[(size_t)r2.x * 8 + c2];     xb[2] = Xv[(size_t)r2.x * 8 + c2 + 1];
        xa[3] = Xv[(size_t)r3.x * 8 + c2];     xb[3] = Xv[(size_t)r3.x * 8 + c2 + 1];
        const float v[4] = {__int_as_float(r0.y), __int_as_float(r1.y),
                            __int_as_float(r2.y), __int_as_float(r3.y)};
#pragma unroll
        for (int j = 0; j < 4; j++) {
            const __half2* ha = (const __half2*)&xa[j];
            const __half2* hb = (const __half2*)&xb[j];
#pragma unroll
            for (int i = 0; i < 4; i++) {
                const float2 fa = __half22float2(ha[i]);
                const float2 fb = __half22float2(hb[i]);
                acc[2 * i]     += v[j] * fa.x;
                acc[2 * i + 1] += v[j] * fa.y;
                acc[8 + 2 * i]     += v[j] * fb.x;
                acc[8 + 2 * i + 1] += v[j] * fb.y;
            }
        }
    }
    for (; e < end; e++) {
        const int2 ee = g_edge[e];
        const float v = __int_as_float(ee.y);
        const uint4 xa = Xv[(size_t)ee.x * 8 + c2];
        const uint4 xb = Xv[(size_t)ee.x * 8 + c2 + 1];
        const __half2* ha = (const __half2*)&xa;
        const __half2* hb = (const __half2*)&xb;
#pragma unroll
        for (int i = 0; i < 4; i++) {
            const float2 fa = __half22float2(ha[i]);
            const float2 fb = __half22float2(hb[i]);
            acc[2 * i] += v * fa.x;
            acc[2 * i + 1] += v * fa.y;
            acc[8 + 2 * i] += v * fb.x;
            acc[8 + 2 * i + 1] += v * fb.y;
        }
    }
    const float* bp = B2 + c2 * 8;
    float* yp = Y + (size_t)row * 64 + c2 * 8;
#pragma unroll
    for (int q = 0; q < 4; q++) {
        const float4 bv = *(const float4*)(bp + q * 4);
        *(float4*)(yp + q * 4) = make_float4(acc[q * 4] + bv.x, acc[q * 4 + 1] + bv.y,
                                             acc[q * 4 + 2] + bv.z, acc[q * 4 + 3] + bv.w);
    }
}

// ---------------------------------------------------------------------------
extern "C" void kernel_launch(void* const* d_in, const int* in_sizes, int n_in,
                              void* d_out, int out_size) {
    const float* x  = (const float*)d_in[0];
    const int*   es = (const int*)d_in[1];
    const int*   ed = (const int*)d_in[2];
    const float* ev = (const float*)d_in[3];
    const float* W1 = (const float*)d_in[4];
    const float* b1 = (const float*)d_in[5];
    const float* W2 = (const float*)d_in[6];
    const float* b2 = (const float*)d_in[7];
    float* out = (float*)d_out;
    const int E = in_sizes[1];

    __half *t1, *t2;
    float* agg1;
    int* degp;
    __nv_bfloat16 *w1hi, *w1lo, *w2hi, *w2lo;
    cudaGetSymbolAddress((void**)&t1, g_t1);
    cudaGetSymbolAddress((void**)&agg1, g_agg1);
    cudaGetSymbolAddress((void**)&t2, g_t2);
    cudaGetSymbolAddress((void**)&degp, g_deg);
    cudaGetSymbolAddress((void**)&w1hi, g_w1hi);
    cudaGetSymbolAddress((void**)&w1lo, g_w1lo);
    cudaGetSymbolAddress((void**)&w2hi, g_w2hi);
    cudaGetSymbolAddress((void**)&w2lo, g_w2lo);

    constexpr int SM1 = (2 * 128 + 2 * 128) * 136 * 2;  // 139,264 B
    constexpr int SM2 = (2 * 128 + 2 * 64) * 136 * 2;   // 104,448 B
    cudaFuncSetAttribute(gemm_mma<128, false>, cudaFuncAttributeMaxDynamicSharedMemorySize, SM1);
    cudaFuncSetAttribute(gemm_mma<64, true>, cudaFuncAttributeMaxDynamicSharedMemorySize, SM2);

    const int eb = (E + 255) / 256;
    const int gemm_blocks = (NN + 127) / 128;  // 782

    // Fork: CSR build on side stream, prep_w1+gemm_l1 on main stream.
    cudaStream_t s1;
    cudaEvent_t evFork, evCsr, evW2;
    cudaStreamCreateWithFlags(&s1, cudaStreamNonBlocking);
    cudaEventCreateWithFlags(&evFork, cudaEventDisableTiming);
    cudaEventCreateWithFlags(&evCsr, cudaEventDisableTiming);
    cudaEventCreateWithFlags(&evW2, cudaEventDisableTiming);

    cudaEventRecord(evFork, 0);
    cudaStreamWaitEvent(s1, evFork, 0);

    // side stream: CSR build (multi-block scan), then W2 prep off the join path
    cudaMemsetAsync(degp, 0, NN * sizeof(int), s1);
    hist_kernel<<<eb, 256, 0, s1>>>(ed, E);
    scan_a<<<NB, 256, 0, s1>>>();
    scan_b<<<1, 512, 0, s1>>>(E);
    scan_c<<<NB, 256, 0, s1>>>();
    scatter_kernel<<<eb, 256, 0, s1>>>(es, ed, ev, E);
    cudaEventRecord(evCsr, s1);
    prep_w<<<32, 256, 0, s1>>>(W2, 64, w2hi, w2lo);
    cudaEventRecord(evW2, s1);

    // main stream: t1 = x @ W1
    prep_w<<<64, 256>>>(W1, 128, w1hi, w1lo);
    gemm_mma<128, false><<<gemm_blocks, 256, SM1>>>(x, nullptr, w1hi, w1lo, t1);

    // join for spmm128: CSR ready (prep_w2 overlaps with spmm128)
    cudaStreamWaitEvent(0, evCsr, 0);
    spmm_gather128<<<(NN * 8 + 255) / 256, 256>>>(t1, agg1);

    // join for gemm_l2: W2 tiles ready
    cudaStreamWaitEvent(0, evW2, 0);
    gemm_mma<64, true><<<gemm_blocks, 256, SM2>>>(agg1, b1, w2hi, w2lo, t2);

    // out = A @ t2 + b2
    spmm_gather64<<<(NN * 4 + 255) / 256, 256>>>(t2, b2, out);
}

// round 16
// speedup vs baseline: 1.0923x; 1.0923x over previous
#include <cuda_runtime.h>
#include <cuda_bf16.h>
#include <cuda_fp16.h>
#include <cstdint>
#include <cstddef>

#define NN 100000
#define NE 1600000
#define IN_DIM 128
#define HID_DIM 128
#define LAT_DIM 64
#define NB 391  // (NN + 255) / 256, scan blocks

// ---------------------------------------------------------------------------
// Scratch (no cudaMalloc allowed)
// ---------------------------------------------------------------------------
__device__ __half g_t1[(size_t)NN * HID_DIM];   // x @ W1           (fp16)
__device__ __half g_agg1[(size_t)NN * HID_DIM]; // A @ t1           (fp16)
__device__ __half g_t2[(size_t)NN * LAT_DIM];   // relu(agg1+b1)@W2 (fp16)
__device__ int    g_deg[NN];
__device__ int    g_off[NN + 1];
__device__ int    g_cur[NN];
__device__ int    g_bsum[512];
__device__ int    g_boff[512];
__device__ int2   g_edge[NE];                   // dst-sorted (src, val_bits)
// W transposed to [N][K=128], bf16 hi/lo split
__device__ __nv_bfloat16 g_w1hi[128 * 128];
__device__ __nv_bfloat16 g_w1lo[128 * 128];
__device__ __nv_bfloat16 g_w2hi[64 * 128];
__device__ __nv_bfloat16 g_w2lo[64 * 128];

// ---------------------------------------------------------------------------
// warp-MMA helpers (baseline PTX, works on plain compute_103 target)
// ---------------------------------------------------------------------------
__device__ __forceinline__ uint32_t smem_u32(const void* p) {
    uint32_t a;
    asm("{ .reg .u64 t; cvta.to.shared.u64 t, %1; cvt.u32.u64 %0, t; }" : "=r"(a) : "l"(p));
    return a;
}
__device__ __forceinline__ void ldsm4(uint32_t addr, uint32_t& r0, uint32_t& r1,
                                      uint32_t& r2, uint32_t& r3) {
    asm volatile("ldmatrix.sync.aligned.m8n8.x4.shared.b16 {%0,%1,%2,%3}, [%4];"
                 : "=r"(r0), "=r"(r1), "=r"(r2), "=r"(r3) : "r"(addr));
}
__device__ __forceinline__ void mma16816(float* d, const uint32_t* a, const uint32_t* b) {
    asm volatile("mma.sync.aligned.m16n8k16.row.col.f32.bf16.bf16.f32 "
                 "{%0,%1,%2,%3}, {%4,%5,%6,%7}, {%8,%9}, {%0,%1,%2,%3};"
                 : "+f"(d[0]), "+f"(d[1]), "+f"(d[2]), "+f"(d[3])
                 : "r"(a[0]), "r"(a[1]), "r"(a[2]), "r"(a[3]), "r"(b[0]), "r"(b[1]));
}
__device__ __forceinline__ uint32_t pack_bf16x2(__nv_bfloat16 a, __nv_bfloat16 b) {
    return (uint32_t)__bfloat16_as_ushort(a) | ((uint32_t)__bfloat16_as_ushort(b) << 16);
}

// ---------------------------------------------------------------------------
// prep_w: W[k][n] row-major -> Wt[n][k] bf16 hi/lo
// ---------------------------------------------------------------------------
__global__ void __launch_bounds__(256) prep_w(const float* __restrict__ W, int N,
                                              __nv_bfloat16* __restrict__ hi,
                                              __nv_bfloat16* __restrict__ lo) {
    const int total = 128 * N;
    for (int idx = blockIdx.x * blockDim.x + threadIdx.x; idx < total;
         idx += gridDim.x * blockDim.x) {
        const int k = idx / N, n = idx % N;
        const float v = W[idx];
        const __nv_bfloat16 h = __float2bfloat16(v);
        const __nv_bfloat16 l = __float2bfloat16(v - __bfloat162float(h));
        hi[n * 128 + k] = h;
        lo[n * 128 + k] = l;
    }
}

// ---------------------------------------------------------------------------
// HMMA GEMM: out16[128 rows, N] = X[rows,128] @ Wt  (bf16-split, 3 passes)
// X_HALF changes ONLY the A-load statement; loop shape identical to champion.
// ---------------------------------------------------------------------------
template <int N_DIM, bool RELU_BIAS, bool X_HALF>
__global__ void __launch_bounds__(256) gemm_mma(const void* __restrict__ Xv,
                                                const float* __restrict__ BIAS,
                                                const __nv_bfloat16* __restrict__ WHI,
                                                const __nv_bfloat16* __restrict__ WLO,
                                                __half* __restrict__ out) {
    extern __shared__ __nv_bfloat16 sm[];
    constexpr int LDS = 136;                 // padded row stride (elements)
    constexpr int AHI = 0;
    constexpr int ALO = 128 * LDS;
    constexpr int BHI = 2 * 128 * LDS;
    constexpr int BLO = BHI + N_DIM * LDS;
    constexpr int WN = N_DIM / 2;            // warp n-extent
    constexpr int NT = WN / 8;               // n-tiles per warp

    const int tid = threadIdx.x;
    const int wid = tid >> 5, lane = tid & 31;
    const int row0 = blockIdx.x * 128;
    const uint32_t smb = smem_u32(sm);

    // copy Wt hi/lo into padded smem rows (16B chunks)
    {
        const uint4* sh = (const uint4*)WHI;
        const uint4* sl = (const uint4*)WLO;
        for (int i = tid; i < N_DIM * 16; i += 256) {
            const int r = i >> 4, c = i & 15;
            *(uint4*)(sm + BHI + r * LDS + c * 8) = sh[i];
            *(uint4*)(sm + BLO + r * LDS + c * 8) = sl[i];
        }
    }

    // load + (optional bias/relu) + hi/lo split-convert the A tile
    {
        const int r = tid >> 1;
        const int kh = (tid & 1) * 64;
        const bool ok = (row0 + r) < NN;
        uint32_t* ahi = (uint32_t*)(sm + AHI + r * LDS + kh);
        uint32_t* alo = (uint32_t*)(sm + ALO + r * LDS + kh);
#pragma unroll
        for (int i = 0; i < 16; i++) {
            float4 v = make_float4(0.f, 0.f, 0.f, 0.f);
            if (ok) {
                if (X_HALF) {
                    const uint2 raw = *(const uint2*)((const __half*)Xv +
                                                      (size_t)(row0 + r) * 128 + kh + i * 4);
                    const float2 t0 = __half22float2(*(const __half2*)&raw.x);
                    const float2 t1 = __half22float2(*(const __half2*)&raw.y);
                    v = make_float4(t0.x, t0.y, t1.x, t1.y);
                } else {
                    v = *(const float4*)((const float*)Xv +
                                         (size_t)(row0 + r) * 128 + kh + i * 4);
                }
                if (RELU_BIAS) {
                    const float4 bv = *(const float4*)(BIAS + kh + i * 4);
                    v.x = fmaxf(v.x + bv.x, 0.f);
                    v.y = fmaxf(v.y + bv.y, 0.f);
                    v.z = fmaxf(v.z + bv.z, 0.f);
                    v.w = fmaxf(v.w + bv.w, 0.f);
                }
            }
            const __nv_bfloat16 h0 = __float2bfloat16(v.x), h1 = __float2bfloat16(v.y);
            const __nv_bfloat16 h2 = __float2bfloat16(v.z), h3 = __float2bfloat16(v.w);
            const __nv_bfloat16 l0 = __float2bfloat16(v.x - __bfloat162float(h0));
            const __nv_bfloat16 l1 = __float2bfloat16(v.y - __bfloat162float(h1));
            const __nv_bfloat16 l2 = __float2bfloat16(v.z - __bfloat162float(h2));
            const __nv_bfloat16 l3 = __float2bfloat16(v.w - __bfloat162float(h3));
            ahi[i * 2] = pack_bf16x2(h0, h1);
            ahi[i * 2 + 1] = pack_bf16x2(h2, h3);
            alo[i * 2] = pack_bf16x2(l0, l1);
            alo[i * 2 + 1] = pack_bf16x2(l2, l3);
        }
    }
    __syncthreads();

    const int m0 = (wid & 3) * 32;
    const int n0 = (wid >> 2) * WN;

    float acc[2][NT][4];
#pragma unroll
    for (int mt = 0; mt < 2; mt++)
#pragma unroll
        for (int nt = 0; nt < NT; nt++)
#pragma unroll
            for (int j = 0; j < 4; j++) acc[mt][nt][j] = 0.f;

#pragma unroll
    for (int p = 0; p < 3; p++) {
        const int aoff = (p == 2) ? ALO : AHI;
        const int boff = (p == 1) ? BLO : BHI;
        const uint32_t abase = smb + 2 * aoff;
        const uint32_t bbase = smb + 2 * boff;
#pragma unroll
        for (int ks = 0; ks < 8; ks++) {
            uint32_t af[2][4];
#pragma unroll
            for (int mt = 0; mt < 2; mt++) {
                const int r = m0 + mt * 16 + (lane & 7) + ((lane >> 3) & 1) * 8;
                const int kk = ks * 16 + (lane >> 4) * 8;
                ldsm4(abase + (uint32_t)(r * LDS + kk) * 2,
                      af[mt][0], af[mt][1], af[mt][2], af[mt][3]);
            }
            uint32_t bf[NT][2];
#pragma unroll
            for (int np = 0; np < NT / 2; np++) {
                const int r = n0 + np * 16 + (lane >> 4) * 8 + (lane & 7);
                const int kk = ks * 16 + ((lane >> 3) & 1) * 8;
                uint32_t t0, t1, t2, t3;
                ldsm4(bbase + (uint32_t)(r * LDS + kk) * 2, t0, t1, t2, t3);
                bf[2 * np][0] = t0; bf[2 * np][1] = t1;
                bf[2 * np + 1][0] = t2; bf[2 * np + 1][1] = t3;
            }
#pragma unroll
            for (int mt = 0; mt < 2; mt++)
#pragma unroll
                for (int nt = 0; nt < NT; nt++) mma16816(acc[mt][nt], af[mt], bf[nt]);
        }
    }

    // epilogue: D frag -> global fp16
#pragma unroll
    for (int mt = 0; mt < 2; mt++) {
        const int r = row0 + m0 + mt * 16 + (lane >> 2);
#pragma unroll
        for (int nt = 0; nt < NT; nt++) {
            const int c = n0 + nt * 8 + (lane & 3) * 2;
            if (r < NN)
                *(__half2*)(out + (size_t)r * N_DIM + c) =
                    __floats2half2_rn(acc[mt][nt][0], acc[mt][nt][1]);
            if (r + 8 < NN)
                *(__half2*)(out + (size_t)(r + 8) * N_DIM + c) =
                    __floats2half2_rn(acc[mt][nt][2], acc[mt][nt][3]);
        }
    }
}

// ---------------------------------------------------------------------------
// CSR build: histogram -> 3-kernel scan -> scatter (deg zeroed via memset)
// ---------------------------------------------------------------------------
__global__ void __launch_bounds__(256) hist_kernel(const int* __restrict__ dst, int E) {
    const int i = blockIdx.x * blockDim.x + threadIdx.x;
    if (i < E) atomicAdd(&g_deg[dst[i]], 1);
}

__global__ void __launch_bounds__(256) scan_a() {
    __shared__ int s[256];
    const int t = threadIdx.x;
    const int i = blockIdx.x * 256 + t;
    s[t] = (i < NN) ? g_deg[i] : 0;
    __syncthreads();
#pragma unroll
    for (int d = 128; d > 0; d >>= 1) {
        if (t < d) s[t] += s[t + d];
        __syncthreads();
    }
    if (t == 0) g_bsum[blockIdx.x] = s[0];
}

__global__ void __launch_bounds__(512) scan_b(int E) {
    __shared__ int s[512];
    const int t = threadIdx.x;
    const int v = (t < NB) ? g_bsum[t] : 0;
    s[t] = v;
    __syncthreads();
    for (int d = 1; d < 512; d <<= 1) {
        const int a = (t >= d) ? s[t - d] : 0;
        __syncthreads();
        s[t] += a;
        __syncthreads();
    }
    if (t < NB) g_boff[t] = s[t] - v;
    if (t == 0) g_off[NN] = E;
}

__global__ void __launch_bounds__(256) scan_c() {
    __shared__ int s[256];
    const int t = threadIdx.x;
    const int i = blockIdx.x * 256 + t;
    const int v = (i < NN) ? g_deg[i] : 0;
    s[t] = v;
    __syncthreads();
    for (int d = 1; d < 256; d <<= 1) {
        const int a = (t >= d) ? s[t - d] : 0;
        __syncthreads();
        s[t] += a;
        __syncthreads();
    }
    if (i < NN) {
        const int excl = s[t] - v + g_boff[blockIdx.x];
        g_off[i] = excl;
        g_cur[i] = excl;
    }
}

__global__ void __launch_bounds__(256) scatter_kernel(const int* __restrict__ src,
                                                      const int* __restrict__ dst,
                                                      const float* __restrict__ vals, int E) {
    const int i = blockIdx.x * blockDim.x + threadIdx.x;
    if (i < E) {
        const int d = dst[i];
        const int p = atomicAdd(&g_cur[d], 1);
        g_edge[p] = make_int2(src[i], __float_as_int(vals[i]));
    }
}

// ---------------------------------------------------------------------------
// gather SpMM: champion structure (16 lanes/row, 4-edge batches);
// spmm128 epilogue now writes fp16 (one 16B store instead of two).
// ---------------------------------------------------------------------------
__global__ void __launch_bounds__(256) spmm_gather128(const __half* __restrict__ X,
                                                      __half* __restrict__ Y) {
    const int row = (blockIdx.x * blockDim.x + threadIdx.x) >> 4;  // 16 lanes/row
    if (row >= NN) return;
    const int col = threadIdx.x & 15;  // uint4 index in 256B fp16 row
    const int beg = g_off[row], end = g_off[row + 1];
    const uint4* Xv = (const uint4*)X;

    float acc[8];
#pragma unroll
    for (int i = 0; i < 8; i++) acc[i] = 0.f;

    int e = beg;
    for (; e + 4 <= end; e += 4) {
        const int2 r0 = g_edge[e], r1 = g_edge[e + 1];
        const int2 r2 = g_edge[e + 2], r3 = g_edge[e + 3];
        const uint4 x0 = Xv[(size_t)r0.x * 16 + col];
        const uint4 x1 = Xv[(size_t)r1.x * 16 + col];
        const uint4 x2 = Xv[(size_t)r2.x * 16 + col];
        const uint4 x3 = Xv[(size_t)r3.x * 16 + col];
        const float v0 = __int_as_float(r0.y), v1 = __int_as_float(r1.y);
        const float v2 = __int_as_float(r2.y), v3 = __int_as_float(r3.y);
        const __half2 *h0 = (const __half2*)&x0, *h1 = (const __half2*)&x1;
        const __half2 *h2 = (const __half2*)&x2, *h3 = (const __half2*)&x3;
#pragma unroll
        for (int i = 0; i < 4; i++) {
            float2 f;
            f = __half22float2(h0[i]); acc[2 * i] += v0 * f.x; acc[2 * i + 1] += v0 * f.y;
            f = __half22float2(h1[i]); acc[2 * i] += v1 * f.x; acc[2 * i + 1] += v1 * f.y;
            f = __half22float2(h2[i]); acc[2 * i] += v2 * f.x; acc[2 * i + 1] += v2 * f.y;
            f = __half22float2(h3[i]); acc[2 * i] += v3 * f.x; acc[2 * i + 1] += v3 * f.y;
        }
    }
    for (; e < end; e++) {
        const int2 ee = g_edge[e];
        const float v = __int_as_float(ee.y);
        const uint4 xv = Xv[(size_t)ee.x * 16 + col];
        const __half2* hp = (const __half2*)&xv;
#pragma unroll
        for (int i = 0; i < 4; i++) {
            const float2 f = __half22float2(hp[i]);
            acc[2 * i] += v * f.x;
            acc[2 * i + 1] += v * f.y;
        }
    }
    uint4 o;
    __half2* op = (__half2*)&o;
#pragma unroll
    for (int i = 0; i < 4; i++) op[i] = __floats2half2_rn(acc[2 * i], acc[2 * i + 1]);
    *(uint4*)(Y + (size_t)row * 128 + col * 8) = o;
}

__global__ void __launch_bounds__(256) spmm_gather64(const __half* __restrict__ X,
                                                     const float* __restrict__ B2,
                                                     float* __restrict__ Y) {
    const int row = (blockIdx.x * blockDim.x + threadIdx.x) >> 3;  // 8 lanes/row
    if (row >= NN) return;
    const int col = threadIdx.x & 7;   // uint4 index in 128B fp16 row
    const int beg = g_off[row], end = g_off[row + 1];
    const uint4* Xv = (const uint4*)X;

    float acc[8];
#pragma unroll
    for (int i = 0; i < 8; i++) acc[i] = 0.f;

    int e = beg;
    for (; e + 4 <= end; e += 4) {
        const int2 r0 = g_edge[e], r1 = g_edge[e + 1];
        const int2 r2 = g_edge[e + 2], r3 = g_edge[e + 3];
        const uint4 x0 = Xv[(size_t)r0.x * 8 + col];
        const uint4 x1 = Xv[(size_t)r1.x * 8 + col];
        const uint4 x2 = Xv[(size_t)r2.x * 8 + col];
        const uint4 x3 = Xv[(size_t)r3.x * 8 + col];
        const float v0 = __int_as_float(r0.y), v1 = __int_as_float(r1.y);
        const float v2 = __int_as_float(r2.y), v3 = __int_as_float(r3.y);
        const __half2 *h0 = (const __half2*)&x0, *h1 = (const __half2*)&x1;
        const __half2 *h2 = (const __half2*)&x2, *h3 = (const __half2*)&x3;
#pragma unroll
        for (int i = 0; i < 4; i++) {
            float2 f;
            f = __half22float2(h0[i]); acc[2 * i] += v0 * f.x; acc[2 * i + 1] += v0 * f.y;
            f = __half22float2(h1[i]); acc[2 * i] += v1 * f.x; acc[2 * i + 1] += v1 * f.y;
            f = __half22float2(h2[i]); acc[2 * i] += v2 * f.x; acc[2 * i + 1] += v2 * f.y;
            f = __half22float2(h3[i]); acc[2 * i] += v3 * f.x; acc[2 * i + 1] += v3 * f.y;
        }
    }
    for (; e < end; e++) {
        const int2 ee = g_edge[e];
        const float v = __int_as_float(ee.y);
        const uint4 xv = Xv[(size_t)ee.x * 8 + col];
        const __half2* hp = (const __half2*)&xv;
#pragma unroll
        for (int i = 0; i < 4; i++) {
            const float2 f = __half22float2(hp[i]);
            acc[2 * i] += v * f.x;
            acc[2 * i + 1] += v * f.y;
        }
    }
    const float4 b0 = *(const float4*)(B2 + col * 8);
    const float4 b1 = *(const float4*)(B2 + col * 8 + 4);
    *(float4*)(Y + (size_t)row * 64 + col * 8) =
        make_float4(acc[0] + b0.x, acc[1] + b0.y, acc[2] + b0.z, acc[3] + b0.w);
    *(float4*)(Y + (size_t)row * 64 + col * 8 + 4) =
        make_float4(acc[4] + b1.x, acc[5] + b1.y, acc[6] + b1.z, acc[7] + b1.w);
}

// ---------------------------------------------------------------------------
extern "C" void kernel_launch(void* const* d_in, const int* in_sizes, int n_in,
                              void* d_out, int out_size) {
    const float* x  = (const float*)d_in[0];
    const int*   es = (const int*)d_in[1];
    const int*   ed = (const int*)d_in[2];
    const float* ev = (const float*)d_in[3];
    const float* W1 = (const float*)d_in[4];
    const float* b1 = (const float*)d_in[5];
    const float* W2 = (const float*)d_in[6];
    const float* b2 = (const float*)d_in[7];
    float* out = (float*)d_out;
    const int E = in_sizes[1];

    __half *t1, *t2, *agg1;
    int* degp;
    __nv_bfloat16 *w1hi, *w1lo, *w2hi, *w2lo;
    cudaGetSymbolAddress((void**)&t1, g_t1);
    cudaGetSymbolAddress((void**)&agg1, g_agg1);
    cudaGetSymbolAddress((void**)&t2, g_t2);
    cudaGetSymbolAddress((void**)&degp, g_deg);
    cudaGetSymbolAddress((void**)&w1hi, g_w1hi);
    cudaGetSymbolAddress((void**)&w1lo, g_w1lo);
    cudaGetSymbolAddress((void**)&w2hi, g_w2hi);
    cudaGetSymbolAddress((void**)&w2lo, g_w2lo);

    constexpr int SM1 = (2 * 128 + 2 * 128) * 136 * 2;  // 139,264 B
    constexpr int SM2 = (2 * 128 + 2 * 64) * 136 * 2;   // 104,448 B
    cudaFuncSetAttribute(gemm_mma<128, false, false>,
                         cudaFuncAttributeMaxDynamicSharedMemorySize, SM1);
    cudaFuncSetAttribute(gemm_mma<64, true, true>,
                         cudaFuncAttributeMaxDynamicSharedMemorySize, SM2);

    const int eb = (E + 255) / 256;
    const int gemm_blocks = (NN + 127) / 128;  // 782

    // Fork: CSR build on side stream, prep_w1+gemm_l1 on main stream.
    cudaStream_t s1;
    cudaEvent_t evFork, evCsr, evW2;
    cudaStreamCreateWithFlags(&s1, cudaStreamNonBlocking);
    cudaEventCreateWithFlags(&evFork, cudaEventDisableTiming);
    cudaEventCreateWithFlags(&evCsr, cudaEventDisableTiming);
    cudaEventCreateWithFlags(&evW2, cudaEventDisableTiming);

    cudaEventRecord(evFork, 0);
    cudaStreamWaitEvent(s1, evFork, 0);

    // side stream: CSR build (multi-block scan), then W2 prep off the join path
    cudaMemsetAsync(degp, 0, NN * sizeof(int), s1);
    hist_kernel<<<eb, 256, 0, s1>>>(ed, E);
    scan_a<<<NB, 256, 0, s1>>>();
    scan_b<<<1, 512, 0, s1>>>(E);
    scan_c<<<NB, 256, 0, s1>>>();
    scatter_kernel<<<eb, 256, 0, s1>>>(es, ed, ev, E);
    cudaEventRecord(evCsr, s1);
    prep_w<<<32, 256, 0, s1>>>(W2, 64, w2hi, w2lo);
    cudaEventRecord(evW2, s1);

    // main stream: t1 = x @ W1
    prep_w<<<64, 256>>>(W1, 128, w1hi, w1lo);
    gemm_mma<128, false, false><<<gemm_blocks, 256, SM1>>>(x, nullptr, w1hi, w1lo, t1);

    // join for spmm128: CSR ready (prep_w2 overlaps with spmm128)
    cudaStreamWaitEvent(0, evCsr, 0);
    spmm_gather128<<<(NN * 16 + 255) / 256, 256>>>(t1, agg1);

    // join for gemm_l2: W2 tiles ready
    cudaStreamWaitEvent(0, evW2, 0);
    gemm_mma<64, true, true><<<gemm_blocks, 256, SM2>>>(agg1, b1, w2hi, w2lo, t2);

    // out = A @ t2 + b2
    spmm_gather64<<<(NN * 8 + 255) / 256, 256>>>(t2, b2, out);
}